// round 3
// baseline (speedup 1.0000x reference)
#include <cuda_runtime.h>
#include <cstdint>

#define BATCH_ 8192
#define DIM_   768
#define DICT_  32768
#define TOPK_  32

// GEMM tile config
#define BM 128
#define BN 128
#define BKX 16

// ---------------------------------------------------------------------------
// Device scratch (allocation-free rule: __device__ globals)
// ---------------------------------------------------------------------------
__device__ float g_WdT[(size_t)DICT_ * DIM_];   // W_dec transposed: [DICT, DIM]
__device__ float g_vals[BATCH_ * TOPK_];
__device__ int   g_idx [BATCH_ * TOPK_];

// ---------------------------------------------------------------------------
// Encode GEMM: C[m,n] = sum_k X[m,k] * W_enc[n,k] + b_enc[n]
// Both operands K-major (row-major with K contiguous). 128x128 tile, BK=16,
// 256 threads, 8x8 per-thread microtile, fp32.
// ---------------------------------------------------------------------------
__global__ __launch_bounds__(256) void encode_gemm(
    const float* __restrict__ A,     // X [BATCH, DIM]
    const float* __restrict__ B,     // W_enc [DICT, DIM]
    const float* __restrict__ bias,  // b_enc [DICT]
    float* __restrict__ C)           // z -> encoded region [BATCH, DICT]
{
    __shared__ float As[BKX][BM + 4];
    __shared__ float Bs[BKX][BN + 4];

    const int tid = threadIdx.x;
    const int m0 = blockIdx.y * BM;
    const int n0 = blockIdx.x * BN;
    const int tx = tid & 15;       // 0..15 -> n microtile
    const int ty = tid >> 4;       // 0..15 -> m microtile
    const int lr = tid >> 2;       // 0..63 load row
    const int lc = (tid & 3) << 2; // 0,4,8,12 load col (float4)

    float acc[8][8];
    #pragma unroll
    for (int i = 0; i < 8; i++)
        #pragma unroll
        for (int j = 0; j < 8; j++) acc[i][j] = 0.f;

    const float* Ab = A + (size_t)m0 * DIM_;
    const float* Bb = B + (size_t)n0 * DIM_;

    for (int k0 = 0; k0 < DIM_; k0 += BKX) {
        #pragma unroll
        for (int s = 0; s < 2; s++) {
            int r = lr + s * 64;
            float4 va = *reinterpret_cast<const float4*>(Ab + (size_t)r * DIM_ + k0 + lc);
            As[lc + 0][r] = va.x; As[lc + 1][r] = va.y;
            As[lc + 2][r] = va.z; As[lc + 3][r] = va.w;
            float4 vb = *reinterpret_cast<const float4*>(Bb + (size_t)r * DIM_ + k0 + lc);
            Bs[lc + 0][r] = vb.x; Bs[lc + 1][r] = vb.y;
            Bs[lc + 2][r] = vb.z; Bs[lc + 3][r] = vb.w;
        }
        __syncthreads();
        #pragma unroll
        for (int kk = 0; kk < BKX; kk++) {
            float a[8], b[8];
            #pragma unroll
            for (int i = 0; i < 8; i++) a[i] = As[kk][ty * 8 + i];
            #pragma unroll
            for (int j = 0; j < 8; j++) b[j] = Bs[kk][tx * 8 + j];
            #pragma unroll
            for (int i = 0; i < 8; i++)
                #pragma unroll
                for (int j = 0; j < 8; j++)
                    acc[i][j] = fmaf(a[i], b[j], acc[i][j]);
        }
        __syncthreads();
    }

    float4 bb0 = *reinterpret_cast<const float4*>(bias + n0 + tx * 8);
    float4 bb1 = *reinterpret_cast<const float4*>(bias + n0 + tx * 8 + 4);
    #pragma unroll
    for (int i = 0; i < 8; i++) {
        size_t off = (size_t)(m0 + ty * 8 + i) * DICT_ + n0 + tx * 8;
        float4 c0 = make_float4(acc[i][0] + bb0.x, acc[i][1] + bb0.y,
                                acc[i][2] + bb0.z, acc[i][3] + bb0.w);
        float4 c1 = make_float4(acc[i][4] + bb1.x, acc[i][5] + bb1.y,
                                acc[i][6] + bb1.z, acc[i][7] + bb1.w);
        *reinterpret_cast<float4*>(C + off)     = c0;
        *reinterpret_cast<float4*>(C + off + 4) = c1;
    }
}

// ---------------------------------------------------------------------------
// Exact top-K per row via 4-pass radix select (8 bits/pass) on the monotonic
// uint transform of fp32. Row staged in 128KB dynamic smem. Tie handling:
// first occurrence (lowest index) kept, matching jax.lax.top_k.
// Sparsifies the row in place and records (val, idx) pairs for decode.
// ---------------------------------------------------------------------------
__device__ __forceinline__ unsigned key_of(float f) {
    unsigned u = __float_as_uint(f);
    return u ^ ((u & 0x80000000u) ? 0xFFFFFFFFu : 0x80000000u);
}

__global__ __launch_bounds__(256) void topk_kernel(float* __restrict__ enc)
{
    extern __shared__ float srow[];   // DICT_ floats = 128KB
    const int row = blockIdx.x;
    const int tid = threadIdx.x;
    float* z = enc + (size_t)row * DICT_;

    // Stage row into smem (coalesced float4)
    {
        float4* s4 = reinterpret_cast<float4*>(srow);
        const float4* z4 = reinterpret_cast<const float4*>(z);
        for (int i = tid; i < DICT_ / 4; i += 256) s4[i] = z4[i];
    }

    __shared__ unsigned hist[256];
    __shared__ unsigned s_prefix;
    __shared__ int s_k;
    __shared__ int eq_cnt, slot;
    __shared__ int   eq_i[1024];
    __shared__ float eq_v[1024];

    unsigned prefix = 0;
    int k = TOPK_;
    __syncthreads();  // smem staging complete

    for (int pass = 0; pass < 4; pass++) {
        const int shift = 24 - pass * 8;
        hist[tid] = 0;
        __syncthreads();
        for (int i = tid; i < DICT_; i += 256) {
            unsigned u = key_of(srow[i]);
            bool match = (pass == 0) ? true : ((u >> (shift + 8)) == prefix);
            if (match) atomicAdd(&hist[(u >> shift) & 255], 1u);
        }
        __syncthreads();
        if (tid == 0) {
            int kk = k;
            int b = 255;
            for (;; b--) {
                int c = (int)hist[b];
                if (c >= kk) break;
                kk -= c;
            }
            s_prefix = (prefix << 8) | (unsigned)b;
            s_k = kk;
        }
        __syncthreads();
        prefix = s_prefix;
        k = s_k;
        __syncthreads();
    }
    const unsigned thresh = prefix;  // exact key of the K-th largest
    const int k_eq = k;              // how many ==thresh to keep (index order)

    if (tid == 0) { eq_cnt = 0; slot = 0; }
    __syncthreads();

    // Sparsify in place (coalesced). Strictly-greater elements are kept
    // unconditionally; equals are collected and resolved below by index.
    for (int i = tid; i < DICT_; i += 256) {
        float f = srow[i];
        unsigned u = key_of(f);
        bool gt = (u > thresh);
        if (gt) {
            int s = atomicAdd(&slot, 1);
            g_vals[row * TOPK_ + s] = f;
            g_idx [row * TOPK_ + s] = i;
        } else if (u == thresh) {
            int e = atomicAdd(&eq_cnt, 1);
            if (e < 1024) { eq_i[e] = i; eq_v[e] = f; }
        }
        z[i] = gt ? f : 0.0f;
    }
    __syncthreads();

    if (tid == 0) {
        int ec = eq_cnt < 1024 ? eq_cnt : 1024;
        int base = TOPK_ - k_eq;   // #gt == TOPK_-k_eq by radix invariant
        for (int s = 0; s < k_eq; s++) {
            int best = 0, bi = 0x7FFFFFFF;
            for (int e = 0; e < ec; e++)
                if (eq_i[e] < bi) { bi = eq_i[e]; best = e; }
            z[bi] = eq_v[best];
            g_vals[row * TOPK_ + base + s] = eq_v[best];
            g_idx [row * TOPK_ + base + s] = bi;
            eq_i[best] = 0x7FFFFFFF;
        }
    }
}

// ---------------------------------------------------------------------------
// W_dec [DIM, DICT] -> g_WdT [DICT, DIM] (32x32 smem tiles)
// ---------------------------------------------------------------------------
__global__ void transpose_wdec(const float* __restrict__ Wd)
{
    __shared__ float tile[32][33];
    int bx = blockIdx.x * 32;   // dict
    int by = blockIdx.y * 32;   // dim
    int tx = threadIdx.x, ty = threadIdx.y;   // 32 x 8
    #pragma unroll
    for (int j = 0; j < 32; j += 8)
        tile[ty + j][tx] = Wd[(size_t)(by + ty + j) * DICT_ + bx + tx];
    __syncthreads();
    #pragma unroll
    for (int j = 0; j < 32; j += 8)
        g_WdT[(size_t)(bx + ty + j) * DIM_ + by + tx] = tile[tx][ty + j];
}

// ---------------------------------------------------------------------------
// Decode: rec[b,:] = b_dec + sum_k vals[b,k] * WdT[idx[b,k],:]
// plus recon_loss = mean_b sum_d (rec - x)^2
// ---------------------------------------------------------------------------
__global__ __launch_bounds__(256) void decode_kernel(
    const float* __restrict__ X, const float* __restrict__ b_dec,
    float* __restrict__ rec, float* __restrict__ loss)
{
    const int row = blockIdx.x;
    const int tid = threadIdx.x;
    __shared__ float sv[TOPK_];
    __shared__ int   si[TOPK_];
    if (tid < TOPK_) { sv[tid] = g_vals[row * TOPK_ + tid];
                       si[tid] = g_idx [row * TOPK_ + tid]; }
    __syncthreads();

    float acc[3];
    #pragma unroll
    for (int j = 0; j < 3; j++) acc[j] = b_dec[tid + j * 256];

    for (int kk = 0; kk < TOPK_; kk++) {
        const float* w = g_WdT + (size_t)si[kk] * DIM_;
        float v = sv[kk];
        #pragma unroll
        for (int j = 0; j < 3; j++)
            acc[j] = fmaf(v, w[tid + j * 256], acc[j]);
    }

    float err = 0.f;
    #pragma unroll
    for (int j = 0; j < 3; j++) {
        int d = tid + j * 256;
        float r = acc[j];
        rec[(size_t)row * DIM_ + d] = r;
        float diff = r - X[(size_t)row * DIM_ + d];
        err = fmaf(diff, diff, err);
    }
    #pragma unroll
    for (int o = 16; o; o >>= 1) err += __shfl_xor_sync(0xFFFFFFFFu, err, o);
    __shared__ float ws[8];
    if ((tid & 31) == 0) ws[tid >> 5] = err;
    __syncthreads();
    if (tid < 8) {
        float e = ws[tid];
        #pragma unroll
        for (int o = 4; o; o >>= 1) e += __shfl_xor_sync(0xFFu, e, o);
        if (tid == 0) atomicAdd(loss, e * (1.0f / BATCH_));
    }
}

__global__ void zero_loss(float* loss) { if (threadIdx.x == 0) *loss = 0.f; }

// ---------------------------------------------------------------------------
// kernel_launch — graph-capturable, allocation-free.
// Output layout (tuple order, flattened):
//   [reconstructed B*DIM | encoded B*DICT | recon_loss 1]
// ---------------------------------------------------------------------------
extern "C" void kernel_launch(void* const* d_in, const int* in_sizes, int n_in,
                              void* d_out, int out_size)
{
    const float* X     = (const float*)d_in[0];
    const float* W_enc = (const float*)d_in[1];
    const float* b_enc = (const float*)d_in[2];
    const float* W_dec = (const float*)d_in[3];
    const float* b_dec = (const float*)d_in[4];

    float* out  = (float*)d_out;
    float* rec  = out;
    float* enc  = out + (size_t)BATCH_ * DIM_;
    float* loss = enc + (size_t)BATCH_ * DICT_;

    // 128KB dynamic smem opt-in for the radix-select kernel (not a stream op;
    // safe under graph capture, idempotent per call).
    cudaFuncSetAttribute(topk_kernel,
                         cudaFuncAttributeMaxDynamicSharedMemorySize,
                         DICT_ * (int)sizeof(float));

    dim3 gemm_grid(DICT_ / BN, BATCH_ / BM);
    encode_gemm<<<gemm_grid, 256>>>(X, W_enc, b_enc, enc);
    topk_kernel<<<BATCH_, 256, DICT_ * sizeof(float)>>>(enc);
    transpose_wdec<<<dim3(DICT_ / 32, DIM_ / 32), dim3(32, 8)>>>(W_dec);
    zero_loss<<<1, 32>>>(loss);
    decode_kernel<<<BATCH_, 256>>>(X, b_dec, rec, loss);
}

// round 6
// speedup vs baseline: 1.8074x; 1.8074x over previous
#include <cuda_runtime.h>
#include <cuda_bf16.h>
#include <cstdint>

#define BATCH_ 8192
#define DIM_   768
#define DICT_  32768
#define TOPK_  32
#define CAND   64

// Split-bf16 GEMM: K' = 3*DIM (hi*hi + hi*lo + lo*hi), single GEMM
#define K2      2304
#define TM      128
#define TN      128
#define BK      32
#define NCH     (K2 / BK)          // 72
#define ASTRIDE 80                 // 64B row + 16B pad: conflict-free ldmatrix
#define A_STAGE (TM * ASTRIDE)     // 10240
#define STAGE_BYTES (2 * A_STAGE)  // 20480
#define STAGES  4
#define SMEM_GEMM (STAGES * STAGE_BYTES)   // 81920

// ---------------------------------------------------------------------------
// Device scratch (allocation-free rule: __device__ globals)
// ---------------------------------------------------------------------------
__device__ __nv_bfloat16 g_XA[(size_t)BATCH_ * K2];  // [Xhi | Xhi | Xlo]
__device__ __nv_bfloat16 g_WB[(size_t)DICT_  * K2];  // [Whi | Wlo | Whi]
__device__ float g_WdT[(size_t)DICT_ * DIM_];        // W_dec transposed
__device__ int   g_cand[BATCH_ * CAND];              // approx top-64 indices
__device__ float g_vals[BATCH_ * TOPK_];
__device__ int   g_idx [BATCH_ * TOPK_];

// ---------------------------------------------------------------------------
// PTX helpers (sm_80+ baseline only — NO tcgen05: harness targets sm_103)
// ---------------------------------------------------------------------------
__device__ __forceinline__ uint32_t smem_u32(const void* p) {
    return (uint32_t)__cvta_generic_to_shared(p);
}

__device__ __forceinline__ void cp_async16(uint32_t dst, const void* src) {
    asm volatile("cp.async.cg.shared.global [%0], [%1], 16;"
                 :: "r"(dst), "l"(src) : "memory");
}

__device__ __forceinline__ void ldsm_x4(uint32_t r[4], uint32_t addr) {
    asm volatile("ldmatrix.sync.aligned.m8n8.x4.shared.b16 {%0,%1,%2,%3}, [%4];"
                 : "=r"(r[0]), "=r"(r[1]), "=r"(r[2]), "=r"(r[3]) : "r"(addr));
}

__device__ __forceinline__ void mma16816(float c[4], const uint32_t a[4],
                                         const uint32_t b[2]) {
    asm volatile(
        "mma.sync.aligned.m16n8k16.row.col.f32.bf16.bf16.f32 "
        "{%0,%1,%2,%3}, {%4,%5,%6,%7}, {%8,%9}, {%0,%1,%2,%3};"
        : "+f"(c[0]), "+f"(c[1]), "+f"(c[2]), "+f"(c[3])
        : "r"(a[0]), "r"(a[1]), "r"(a[2]), "r"(a[3]), "r"(b[0]), "r"(b[1]));
}

// ---------------------------------------------------------------------------
// Split conversion: fp32 -> (bf16 hi, bf16 lo), concatenated K'=2304 layout
// ---------------------------------------------------------------------------
__global__ __launch_bounds__(256) void split_x(const float* __restrict__ X) {
    int idx = blockIdx.x * 256 + threadIdx.x;
    if (idx >= BATCH_ * DIM_) return;
    int r = idx / DIM_, c = idx % DIM_;
    float x = X[idx];
    __nv_bfloat16 hi = __float2bfloat16(x);
    __nv_bfloat16 lo = __float2bfloat16(x - __bfloat162float(hi));
    size_t base = (size_t)r * K2;
    g_XA[base + c]            = hi;
    g_XA[base + DIM_ + c]     = hi;
    g_XA[base + 2 * DIM_ + c] = lo;
}

__global__ __launch_bounds__(256) void split_w(const float* __restrict__ W) {
    int idx = blockIdx.x * 256 + threadIdx.x;
    if (idx >= DICT_ * DIM_) return;
    int r = idx / DIM_, c = idx % DIM_;
    float w = W[idx];
    __nv_bfloat16 hi = __float2bfloat16(w);
    __nv_bfloat16 lo = __float2bfloat16(w - __bfloat162float(hi));
    size_t base = (size_t)r * K2;
    g_WB[base + c]            = hi;
    g_WB[base + DIM_ + c]     = lo;
    g_WB[base + 2 * DIM_ + c] = hi;
}

// ---------------------------------------------------------------------------
// HMMA encode GEMM (approximate filter): C[m,n] = sum_k XA[m,k]*WB[n,k]
// 128x128 CTA tile, BK=32, 8 warps (64x32 warp tiles), cp.async 4-slot ring.
// (bias omitted here; exact bias added in refine; approx z only ranks.)
// NOTE: bias DOES matter for ranking! b_enc varies per column. Keep it.
// ---------------------------------------------------------------------------
__device__ __forceinline__ void load_stage_g(uint32_t sbase, int slot, int k0,
                                             int m0, int n0, int tid) {
    uint32_t sA = sbase + slot * STAGE_BYTES;
    uint32_t sB = sA + A_STAGE;
    const __nv_bfloat16* Ag = g_XA + (size_t)m0 * K2 + k0;
    const __nv_bfloat16* Bg = g_WB + (size_t)n0 * K2 + k0;
    const int lrow = tid >> 2;       // 0..63
    const int lch  = tid & 3;        // 16B chunk within 64B row
    #pragma unroll
    for (int it = 0; it < 2; it++) {
        int row = lrow + it * 64;
        cp_async16(sA + row * ASTRIDE + lch * 16, Ag + (size_t)row * K2 + lch * 8);
        cp_async16(sB + row * ASTRIDE + lch * 16, Bg + (size_t)row * K2 + lch * 8);
    }
}

__global__ __launch_bounds__(256, 2) void encode_gemm_mma(
    const float* __restrict__ bias, float* __restrict__ C)
{
    extern __shared__ char smem[];
    const uint32_t sbase = smem_u32(smem);
    const int tid  = threadIdx.x;
    const int lane = tid & 31;
    const int wid  = tid >> 5;
    const int m0 = blockIdx.x * TM;
    const int n0 = blockIdx.y * TN;
    const int wm = (wid & 1) * 64;   // warp M offset
    const int wn = (wid >> 1) * 32;  // warp N offset

    float acc[4][4][4];
    #pragma unroll
    for (int mi = 0; mi < 4; mi++)
        #pragma unroll
        for (int ni = 0; ni < 4; ni++)
            #pragma unroll
            for (int r = 0; r < 4; r++) acc[mi][ni][r] = 0.f;

    #pragma unroll
    for (int s = 0; s < 3; s++) {
        load_stage_g(sbase, s, s * BK, m0, n0, tid);
        asm volatile("cp.async.commit_group;" ::: "memory");
    }

    for (int i = 0; i < NCH; i++) {
        asm volatile("cp.async.wait_group 2;" ::: "memory");
        __syncthreads();

        if (i + 3 < NCH)
            load_stage_g(sbase, (i + 3) & 3, (i + 3) * BK, m0, n0, tid);
        asm volatile("cp.async.commit_group;" ::: "memory");

        const uint32_t sA = sbase + (i & 3) * STAGE_BYTES;
        const uint32_t sB = sA + A_STAGE;
        const int g = lane >> 3;

        #pragma unroll
        for (int ks = 0; ks < 2; ks++) {
            uint32_t a[4][4], b[2][4];
            #pragma unroll
            for (int mi = 0; mi < 4; mi++)
                ldsm_x4(a[mi], sA + (wm + mi * 16 + (lane & 15)) * ASTRIDE
                               + ks * 32 + (lane >> 4) * 16);
            #pragma unroll
            for (int nj = 0; nj < 2; nj++)
                ldsm_x4(b[nj], sB + (wn + nj * 16 + (g >> 1) * 8 + (lane & 7)) * ASTRIDE
                               + ks * 32 + (g & 1) * 16);
            #pragma unroll
            for (int mi = 0; mi < 4; mi++)
                #pragma unroll
                for (int ni = 0; ni < 4; ni++)
                    mma16816(acc[mi][ni], a[mi], &b[ni >> 1][(ni & 1) * 2]);
        }
    }

    #pragma unroll
    for (int mi = 0; mi < 4; mi++) {
        int r0 = m0 + wm + mi * 16 + (lane >> 2);
        #pragma unroll
        for (int ni = 0; ni < 4; ni++) {
            int col = n0 + wn + ni * 8 + (lane & 3) * 2;
            float2 bv = *reinterpret_cast<const float2*>(bias + col);
            float2 v0 = make_float2(acc[mi][ni][0] + bv.x, acc[mi][ni][1] + bv.y);
            float2 v1 = make_float2(acc[mi][ni][2] + bv.x, acc[mi][ni][3] + bv.y);
            *reinterpret_cast<float2*>(C + (size_t)r0 * DICT_ + col)       = v0;
            *reinterpret_cast<float2*>(C + (size_t)(r0 + 8) * DICT_ + col) = v1;
        }
    }
}

// ---------------------------------------------------------------------------
// Candidate selection: top-CAND indices per row (approx, radix select) and
// zero the entire encoded row. Exact values/indices resolved by refine.
// ---------------------------------------------------------------------------
__device__ __forceinline__ unsigned key_of(float f) {
    unsigned u = __float_as_uint(f);
    return u ^ ((u & 0x80000000u) ? 0xFFFFFFFFu : 0x80000000u);
}

__global__ __launch_bounds__(256) void topk_cand(float* __restrict__ enc)
{
    extern __shared__ float srow[];   // DICT_ floats = 128KB
    const int row = blockIdx.x;
    const int tid = threadIdx.x;
    float* z = enc + (size_t)row * DICT_;

    {
        float4* s4 = reinterpret_cast<float4*>(srow);
        const float4* z4 = reinterpret_cast<const float4*>(z);
        for (int i = tid; i < DICT_ / 4; i += 256) s4[i] = z4[i];
    }

    __shared__ unsigned hist[256];
    __shared__ unsigned s_prefix;
    __shared__ int s_k;
    __shared__ int eq_cnt, slot;
    __shared__ int eq_i[1024];

    unsigned prefix = 0;
    int k = CAND;
    __syncthreads();

    for (int pass = 0; pass < 4; pass++) {
        const int shift = 24 - pass * 8;
        hist[tid] = 0;
        __syncthreads();
        for (int i = tid; i < DICT_; i += 256) {
            unsigned u = key_of(srow[i]);
            bool match = (pass == 0) ? true : ((u >> (shift + 8)) == prefix);
            if (match) atomicAdd(&hist[(u >> shift) & 255], 1u);
        }
        __syncthreads();
        if (tid == 0) {
            int kk = k;
            int b = 255;
            for (;; b--) {
                int c = (int)hist[b];
                if (c >= kk) break;
                kk -= c;
            }
            s_prefix = (prefix << 8) | (unsigned)b;
            s_k = kk;
        }
        __syncthreads();
        prefix = s_prefix;
        k = s_k;
        __syncthreads();
    }
    const unsigned thresh = prefix;
    const int k_eq = k;

    if (tid == 0) { eq_cnt = 0; slot = 0; }
    __syncthreads();

    // Collect candidates (from smem) — order irrelevant (refine re-sorts)
    for (int i = tid; i < DICT_; i += 256) {
        unsigned u = key_of(srow[i]);
        if (u > thresh) {
            int s = atomicAdd(&slot, 1);
            g_cand[row * CAND + s] = i;
        } else if (u == thresh) {
            int e = atomicAdd(&eq_cnt, 1);
            if (e < 1024) eq_i[e] = i;
        }
    }

    // Zero the whole row (refine scatters exact values afterwards)
    {
        float4 zero = make_float4(0.f, 0.f, 0.f, 0.f);
        float4* z4 = reinterpret_cast<float4*>(z);
        for (int i = tid; i < DICT_ / 4; i += 256) z4[i] = zero;
    }
    __syncthreads();

    if (tid == 0) {
        int base = CAND - k_eq;   // #gt == CAND - k_eq by radix invariant
        for (int s = 0; s < k_eq; s++)
            g_cand[row * CAND + base + s] = eq_i[s];
    }
}

// ---------------------------------------------------------------------------
// Refine: exact fp32 recompute of the CAND candidate activations, exact
// top-32 with first-index tie-break, scatter into enc + decode buffers.
// ---------------------------------------------------------------------------
__device__ __forceinline__ unsigned long long sel_key(float v, int idx) {
    return ((unsigned long long)key_of(v) << 32) | (unsigned)(0x7FFFFFFF - idx);
}

__global__ __launch_bounds__(256) void refine_kernel(
    const float* __restrict__ X, const float* __restrict__ W_enc,
    const float* __restrict__ b_enc, float* __restrict__ enc)
{
    const int row = blockIdx.x;
    const int tid = threadIdx.x;
    const int w = tid >> 5, lane = tid & 31;
    __shared__ float sx[DIM_];
    __shared__ float cv[CAND];
    __shared__ int   ci[CAND];

    for (int i = tid; i < DIM_ / 4; i += 256)
        reinterpret_cast<float4*>(sx)[i] =
            reinterpret_cast<const float4*>(X + (size_t)row * DIM_)[i];
    if (tid < CAND) ci[tid] = g_cand[row * CAND + tid];
    __syncthreads();

    // Exact fp32 dot per candidate: warp w handles candidates w, w+8, ...
    for (int c = w; c < CAND; c += 8) {
        const float* wr = W_enc + (size_t)ci[c] * DIM_;
        float s = 0.f;
        #pragma unroll
        for (int j = lane * 4; j < DIM_; j += 128) {
            float4 a = *reinterpret_cast<const float4*>(sx + j);
            float4 b = *reinterpret_cast<const float4*>(wr + j);
            s = fmaf(a.x, b.x, s); s = fmaf(a.y, b.y, s);
            s = fmaf(a.z, b.z, s); s = fmaf(a.w, b.w, s);
        }
        #pragma unroll
        for (int o = 16; o; o >>= 1) s += __shfl_xor_sync(0xFFFFFFFFu, s, o);
        if (lane == 0) cv[c] = s + b_enc[ci[c]];
    }
    __syncthreads();

    // Warp 0: exact top-32 (val desc, idx asc). Keys unique (idx embedded).
    if (w == 0) {
        unsigned long long ka = sel_key(cv[lane],      ci[lane]);
        unsigned long long kb = sel_key(cv[lane + 32], ci[lane + 32]);
        for (int s = 0; s < TOPK_; s++) {
            unsigned long long m = ka > kb ? ka : kb;
            #pragma unroll
            for (int o = 16; o; o >>= 1) {
                unsigned long long t = __shfl_xor_sync(0xFFFFFFFFu, m, o);
                if (t > m) m = t;
            }
            if (ka == m) {
                int idx = ci[lane]; float v = cv[lane];
                enc[(size_t)row * DICT_ + idx] = v;
                g_vals[row * TOPK_ + s] = v;
                g_idx [row * TOPK_ + s] = idx;
                ka = 0ull;
            } else if (kb == m) {
                int idx = ci[lane + 32]; float v = cv[lane + 32];
                enc[(size_t)row * DICT_ + idx] = v;
                g_vals[row * TOPK_ + s] = v;
                g_idx [row * TOPK_ + s] = idx;
                kb = 0ull;
            }
        }
    }
}

// ---------------------------------------------------------------------------
// W_dec [DIM, DICT] -> g_WdT [DICT, DIM]
// ---------------------------------------------------------------------------
__global__ void transpose_wdec(const float* __restrict__ Wd)
{
    __shared__ float tile[32][33];
    int bx = blockIdx.x * 32;
    int by = blockIdx.y * 32;
    int tx = threadIdx.x, ty = threadIdx.y;
    #pragma unroll
    for (int j = 0; j < 32; j += 8)
        tile[ty + j][tx] = Wd[(size_t)(by + ty + j) * DICT_ + bx + tx];
    __syncthreads();
    #pragma unroll
    for (int j = 0; j < 32; j += 8)
        g_WdT[(size_t)(bx + ty + j) * DIM_ + by + tx] = tile[tx][ty + j];
}

// ---------------------------------------------------------------------------
// Decode + loss
// ---------------------------------------------------------------------------
__global__ __launch_bounds__(256) void decode_kernel(
    const float* __restrict__ X, const float* __restrict__ b_dec,
    float* __restrict__ rec, float* __restrict__ loss)
{
    const int row = blockIdx.x;
    const int tid = threadIdx.x;
    __shared__ float sv[TOPK_];
    __shared__ int   si[TOPK_];
    if (tid < TOPK_) { sv[tid] = g_vals[row * TOPK_ + tid];
                       si[tid] = g_idx [row * TOPK_ + tid]; }
    __syncthreads();

    float acc[3];
    #pragma unroll
    for (int j = 0; j < 3; j++) acc[j] = b_dec[tid + j * 256];

    for (int kk = 0; kk < TOPK_; kk++) {
        const float* w = g_WdT + (size_t)si[kk] * DIM_;
        float v = sv[kk];
        #pragma unroll
        for (int j = 0; j < 3; j++)
            acc[j] = fmaf(v, w[tid + j * 256], acc[j]);
    }

    float err = 0.f;
    #pragma unroll
    for (int j = 0; j < 3; j++) {
        int d = tid + j * 256;
        float r = acc[j];
        rec[(size_t)row * DIM_ + d] = r;
        float diff = r - X[(size_t)row * DIM_ + d];
        err = fmaf(diff, diff, err);
    }
    #pragma unroll
    for (int o = 16; o; o >>= 1) err += __shfl_xor_sync(0xFFFFFFFFu, err, o);
    __shared__ float ws[8];
    if ((tid & 31) == 0) ws[tid >> 5] = err;
    __syncthreads();
    if (tid < 8) {
        float e = ws[tid];
        #pragma unroll
        for (int o = 4; o; o >>= 1) e += __shfl_xor_sync(0xFFu, e, o);
        if (tid == 0) atomicAdd(loss, e * (1.0f / BATCH_));
    }
}

__global__ void zero_loss(float* loss) { if (threadIdx.x == 0) *loss = 0.f; }

// ---------------------------------------------------------------------------
// kernel_launch
// ---------------------------------------------------------------------------
extern "C" void kernel_launch(void* const* d_in, const int* in_sizes, int n_in,
                              void* d_out, int out_size)
{
    const float* X     = (const float*)d_in[0];
    const float* W_enc = (const float*)d_in[1];
    const float* b_enc = (const float*)d_in[2];
    const float* W_dec = (const float*)d_in[3];
    const float* b_dec = (const float*)d_in[4];

    float* out  = (float*)d_out;
    float* rec  = out;
    float* enc  = out + (size_t)BATCH_ * DIM_;
    float* loss = enc + (size_t)BATCH_ * DICT_;

    cudaFuncSetAttribute(topk_cand,
                         cudaFuncAttributeMaxDynamicSharedMemorySize,
                         DICT_ * (int)sizeof(float));
    cudaFuncSetAttribute(encode_gemm_mma,
                         cudaFuncAttributeMaxDynamicSharedMemorySize,
                         SMEM_GEMM);

    split_x<<<(BATCH_ * DIM_ + 255) / 256, 256>>>(X);
    split_w<<<(DICT_ * DIM_ + 255) / 256, 256>>>(W_enc);

    // grid.x = M tiles (fast-varying) so a wave of CTAs shares B tiles in L2
    dim3 gg(BATCH_ / TM, DICT_ / TN);
    encode_gemm_mma<<<gg, 256, SMEM_GEMM>>>(b_enc, enc);

    topk_cand<<<BATCH_, 256, DICT_ * sizeof(float)>>>(enc);
    refine_kernel<<<BATCH_, 256>>>(X, W_enc, b_enc, enc);
    transpose_wdec<<<dim3(DICT_ / 32, DIM_ / 32), dim3(32, 8)>>>(W_dec);
    zero_loss<<<1, 32>>>(loss);
    decode_kernel<<<BATCH_, 256>>>(X, b_dec, rec, loss);
}

// round 8
// speedup vs baseline: 4.9426x; 2.7346x over previous
#include <cuda_runtime.h>
#include <cuda_bf16.h>
#include <cstdint>

#define BATCH_ 8192
#define DIM_   768
#define DICT_  32768
#define TOPK_  32
#define CAND   64

// Plain bf16 filter GEMM (refine makes the final result exact): K = 768
#define K2      768
#define TM      128
#define TN      128
#define BK      32
#define NCH     (K2 / BK)          // 24
#define ASTRIDE 80                 // 64B row + 16B pad: conflict-free ldmatrix
#define A_STAGE (TM * ASTRIDE)     // 10240
#define STAGE_BYTES (2 * A_STAGE)  // 20480
#define STAGES  4
#define SMEM_GEMM (STAGES * STAGE_BYTES)   // 81920

// ---------------------------------------------------------------------------
// Device scratch (allocation-free rule: __device__ globals)
// ---------------------------------------------------------------------------
__device__ __nv_bfloat16 g_XA[(size_t)BATCH_ * K2];    // bf16(X)
__device__ __nv_bfloat16 g_WB[(size_t)DICT_  * K2];    // bf16(W_enc)
__device__ __nv_bfloat16 g_Z [(size_t)BATCH_ * DICT_]; // approx z (bf16)
__device__ float g_WdT[(size_t)DICT_ * DIM_];          // W_dec transposed
__device__ int   g_cand[BATCH_ * CAND];                // approx top-64 indices
__device__ float g_vals[BATCH_ * TOPK_];
__device__ int   g_idx [BATCH_ * TOPK_];

// ---------------------------------------------------------------------------
// PTX helpers (sm_80+ baseline only — NO tcgen05: harness targets sm_103)
// ---------------------------------------------------------------------------
__device__ __forceinline__ uint32_t smem_u32(const void* p) {
    return (uint32_t)__cvta_generic_to_shared(p);
}

__device__ __forceinline__ void cp_async16(uint32_t dst, const void* src) {
    asm volatile("cp.async.cg.shared.global [%0], [%1], 16;"
                 :: "r"(dst), "l"(src) : "memory");
}

__device__ __forceinline__ void ldsm_x4(uint32_t r[4], uint32_t addr) {
    asm volatile("ldmatrix.sync.aligned.m8n8.x4.shared.b16 {%0,%1,%2,%3}, [%4];"
                 : "=r"(r[0]), "=r"(r[1]), "=r"(r[2]), "=r"(r[3]) : "r"(addr));
}

__device__ __forceinline__ void mma16816(float c[4], const uint32_t a[4],
                                         const uint32_t b[2]) {
    asm volatile(
        "mma.sync.aligned.m16n8k16.row.col.f32.bf16.bf16.f32 "
        "{%0,%1,%2,%3}, {%4,%5,%6,%7}, {%8,%9}, {%0,%1,%2,%3};"
        : "+f"(c[0]), "+f"(c[1]), "+f"(c[2]), "+f"(c[3])
        : "r"(a[0]), "r"(a[1]), "r"(a[2]), "r"(a[3]), "r"(b[0]), "r"(b[1]));
}

// ---------------------------------------------------------------------------
// fp32 -> bf16 conversions (vectorized) + output-zero kernel
// ---------------------------------------------------------------------------
__global__ __launch_bounds__(256) void cvt_x(const float* __restrict__ X) {
    int i = blockIdx.x * 256 + threadIdx.x;
    if (i >= BATCH_ * DIM_ / 4) return;
    float4 v = reinterpret_cast<const float4*>(X)[i];
    reinterpret_cast<__nv_bfloat162*>(g_XA)[i*2]   = __float22bfloat162_rn(make_float2(v.x, v.y));
    reinterpret_cast<__nv_bfloat162*>(g_XA)[i*2+1] = __float22bfloat162_rn(make_float2(v.z, v.w));
}

__global__ __launch_bounds__(256) void cvt_w(const float* __restrict__ W) {
    int i = blockIdx.x * 256 + threadIdx.x;
    if (i >= DICT_ * DIM_ / 4) return;
    float4 v = reinterpret_cast<const float4*>(W)[i];
    reinterpret_cast<__nv_bfloat162*>(g_WB)[i*2]   = __float22bfloat162_rn(make_float2(v.x, v.y));
    reinterpret_cast<__nv_bfloat162*>(g_WB)[i*2+1] = __float22bfloat162_rn(make_float2(v.z, v.w));
}

__global__ __launch_bounds__(256) void zero_enc(float* __restrict__ enc) {
    size_t i = (size_t)blockIdx.x * 256 + threadIdx.x;
    reinterpret_cast<float4*>(enc)[i] = make_float4(0.f, 0.f, 0.f, 0.f);
}

// ---------------------------------------------------------------------------
// HMMA filter GEMM: Z[m,n] = bf16( sum_k XA[m,k]*WB[n,k] + bias[n] )
// ---------------------------------------------------------------------------
__device__ __forceinline__ void load_stage_g(uint32_t sbase, int slot, int k0,
                                             int m0, int n0, int tid) {
    uint32_t sA = sbase + slot * STAGE_BYTES;
    uint32_t sB = sA + A_STAGE;
    const __nv_bfloat16* Ag = g_XA + (size_t)m0 * K2 + k0;
    const __nv_bfloat16* Bg = g_WB + (size_t)n0 * K2 + k0;
    const int lrow = tid >> 2;
    const int lch  = tid & 3;
    #pragma unroll
    for (int it = 0; it < 2; it++) {
        int row = lrow + it * 64;
        cp_async16(sA + row * ASTRIDE + lch * 16, Ag + (size_t)row * K2 + lch * 8);
        cp_async16(sB + row * ASTRIDE + lch * 16, Bg + (size_t)row * K2 + lch * 8);
    }
}

__global__ __launch_bounds__(256, 2) void encode_gemm_mma(
    const float* __restrict__ bias)
{
    extern __shared__ char smem[];
    const uint32_t sbase = smem_u32(smem);
    const int tid  = threadIdx.x;
    const int lane = tid & 31;
    const int wid  = tid >> 5;
    const int m0 = blockIdx.x * TM;
    const int n0 = blockIdx.y * TN;
    const int wm = (wid & 1) * 64;
    const int wn = (wid >> 1) * 32;

    float acc[4][4][4];
    #pragma unroll
    for (int mi = 0; mi < 4; mi++)
        #pragma unroll
        for (int ni = 0; ni < 4; ni++)
            #pragma unroll
            for (int r = 0; r < 4; r++) acc[mi][ni][r] = 0.f;

    #pragma unroll
    for (int s = 0; s < 3; s++) {
        load_stage_g(sbase, s, s * BK, m0, n0, tid);
        asm volatile("cp.async.commit_group;" ::: "memory");
    }

    for (int i = 0; i < NCH; i++) {
        asm volatile("cp.async.wait_group 2;" ::: "memory");
        __syncthreads();

        if (i + 3 < NCH)
            load_stage_g(sbase, (i + 3) & 3, (i + 3) * BK, m0, n0, tid);
        asm volatile("cp.async.commit_group;" ::: "memory");

        const uint32_t sA = sbase + (i & 3) * STAGE_BYTES;
        const uint32_t sB = sA + A_STAGE;
        const int g = lane >> 3;

        #pragma unroll
        for (int ks = 0; ks < 2; ks++) {
            uint32_t a[4][4], b[2][4];
            #pragma unroll
            for (int mi = 0; mi < 4; mi++)
                ldsm_x4(a[mi], sA + (wm + mi * 16 + (lane & 15)) * ASTRIDE
                               + ks * 32 + (lane >> 4) * 16);
            #pragma unroll
            for (int nj = 0; nj < 2; nj++)
                ldsm_x4(b[nj], sB + (wn + nj * 16 + (g >> 1) * 8 + (lane & 7)) * ASTRIDE
                               + ks * 32 + (g & 1) * 16);
            #pragma unroll
            for (int mi = 0; mi < 4; mi++)
                #pragma unroll
                for (int ni = 0; ni < 4; ni++)
                    mma16816(acc[mi][ni], a[mi], &b[ni >> 1][(ni & 1) * 2]);
        }
    }

    #pragma unroll
    for (int mi = 0; mi < 4; mi++) {
        int r0 = m0 + wm + mi * 16 + (lane >> 2);
        #pragma unroll
        for (int ni = 0; ni < 4; ni++) {
            int col = n0 + wn + ni * 8 + (lane & 3) * 2;
            float2 bv = *reinterpret_cast<const float2*>(bias + col);
            __nv_bfloat162 v0 = __float22bfloat162_rn(
                make_float2(acc[mi][ni][0] + bv.x, acc[mi][ni][1] + bv.y));
            __nv_bfloat162 v1 = __float22bfloat162_rn(
                make_float2(acc[mi][ni][2] + bv.x, acc[mi][ni][3] + bv.y));
            *reinterpret_cast<__nv_bfloat162*>(g_Z + (size_t)r0 * DICT_ + col)       = v0;
            *reinterpret_cast<__nv_bfloat162*>(g_Z + (size_t)(r0 + 8) * DICT_ + col) = v1;
        }
    }
}

// ---------------------------------------------------------------------------
// Candidate selection on bf16 z: top-CAND indices per row.
// Three FULL scans of the 64KB smem row (no capped lists -> no overflow):
//   scan1: histogram of 16-bit key's high byte  -> bhi, keq1
//   scan2: histogram of low byte where hi==bhi  -> blo, keq2
//   scan3: emit  hi>bhi | (hi==bhi && lo>blo) | first keq2 of lo==blo
// Counting invariant => exactly CAND emissions. Boundary ties arbitrary —
// safe: rank32->64 gap (~0.12) >> bf16-filter z error (~0.006); refine is
// exact fp32 regardless.
// ---------------------------------------------------------------------------
__device__ __forceinline__ unsigned key16(unsigned h) {
    return h ^ ((h & 0x8000u) ? 0xFFFFu : 0x8000u);
}

__global__ __launch_bounds__(256) void topk_cand()
{
    extern __shared__ unsigned short srow16[];   // DICT_ uint16 = 64KB
    const int row = blockIdx.x;
    const int tid = threadIdx.x;

    {
        const uint4* z4 = reinterpret_cast<const uint4*>(g_Z + (size_t)row * DICT_);
        uint4* s4 = reinterpret_cast<uint4*>(srow16);
        for (int i = tid; i < DICT_ * 2 / 16; i += 256) s4[i] = z4[i];
    }

    __shared__ unsigned hist[256];
    __shared__ int s_b, s_k, s_b2, s_k2, nslot, eq2;

    if (tid == 0) { nslot = 0; eq2 = 0; }
    hist[tid] = 0;
    __syncthreads();

    // scan1: high-byte histogram (2 elems per 32-bit smem read)
    for (int i = tid; i < DICT_ / 2; i += 256) {
        unsigned v = reinterpret_cast<unsigned*>(srow16)[i];
        atomicAdd(&hist[key16(v & 0xFFFFu) >> 8], 1u);
        atomicAdd(&hist[key16(v >> 16) >> 8], 1u);
    }
    __syncthreads();
    if (tid == 0) {
        int kk = CAND, b = 255;
        for (;; b--) { int c = (int)hist[b]; if (c >= kk) break; kk -= c; }
        s_b = b; s_k = kk;
    }
    __syncthreads();
    const unsigned bhi = (unsigned)s_b;
    const int keq1 = s_k;
    hist[tid] = 0;
    __syncthreads();

    // scan2: low-byte histogram restricted to hi == bhi
    for (int i = tid; i < DICT_ / 2; i += 256) {
        unsigned v = reinterpret_cast<unsigned*>(srow16)[i];
        unsigned k0 = key16(v & 0xFFFFu);
        unsigned k1 = key16(v >> 16);
        if ((k0 >> 8) == bhi) atomicAdd(&hist[k0 & 0xFFu], 1u);
        if ((k1 >> 8) == bhi) atomicAdd(&hist[k1 & 0xFFu], 1u);
    }
    __syncthreads();
    if (tid == 0) {
        int kk = keq1, b = 255;
        for (;; b--) { int c = (int)hist[b]; if (c >= kk) break; kk -= c; }
        s_b2 = b; s_k2 = kk;
    }
    __syncthreads();
    const unsigned blo = (unsigned)s_b2;
    const int keq2 = s_k2;

    // scan3: emit exactly CAND candidate indices
    for (int i = tid; i < DICT_; i += 256) {
        unsigned k = key16(srow16[i]);
        unsigned hi = k >> 8, lo = k & 0xFFu;
        if (hi > bhi || (hi == bhi && lo > blo)) {
            int s = atomicAdd(&nslot, 1);
            g_cand[row * CAND + s] = i;
        } else if (hi == bhi && lo == blo) {
            int e = atomicAdd(&eq2, 1);
            if (e < keq2) {
                int s = atomicAdd(&nslot, 1);
                g_cand[row * CAND + s] = i;
            }
        }
    }
}

// ---------------------------------------------------------------------------
// Refine: exact fp32 recompute of the CAND candidates, exact top-32 with
// first-index tie-break, scatter into enc + decode buffers.
// ---------------------------------------------------------------------------
__device__ __forceinline__ unsigned key_of(float f) {
    unsigned u = __float_as_uint(f);
    return u ^ ((u & 0x80000000u) ? 0xFFFFFFFFu : 0x80000000u);
}

__device__ __forceinline__ unsigned long long sel_key(float v, int idx) {
    return ((unsigned long long)key_of(v) << 32) | (unsigned)(0x7FFFFFFF - idx);
}

__global__ __launch_bounds__(256) void refine_kernel(
    const float* __restrict__ X, const float* __restrict__ W_enc,
    const float* __restrict__ b_enc, float* __restrict__ enc)
{
    const int row = blockIdx.x;
    const int tid = threadIdx.x;
    const int w = tid >> 5, lane = tid & 31;
    __shared__ float sx[DIM_];
    __shared__ float cv[CAND];
    __shared__ int   ci[CAND];

    for (int i = tid; i < DIM_ / 4; i += 256)
        reinterpret_cast<float4*>(sx)[i] =
            reinterpret_cast<const float4*>(X + (size_t)row * DIM_)[i];
    if (tid < CAND) ci[tid] = g_cand[row * CAND + tid];
    __syncthreads();

    for (int c = w; c < CAND; c += 8) {
        const float* wr = W_enc + (size_t)ci[c] * DIM_;
        float s = 0.f;
        #pragma unroll
        for (int j = lane * 4; j < DIM_; j += 128) {
            float4 a = *reinterpret_cast<const float4*>(sx + j);
            float4 b = *reinterpret_cast<const float4*>(wr + j);
            s = fmaf(a.x, b.x, s); s = fmaf(a.y, b.y, s);
            s = fmaf(a.z, b.z, s); s = fmaf(a.w, b.w, s);
        }
        #pragma unroll
        for (int o = 16; o; o >>= 1) s += __shfl_xor_sync(0xFFFFFFFFu, s, o);
        if (lane == 0) cv[c] = s + b_enc[ci[c]];
    }
    __syncthreads();

    if (w == 0) {
        unsigned long long ka = sel_key(cv[lane],      ci[lane]);
        unsigned long long kb = sel_key(cv[lane + 32], ci[lane + 32]);
        for (int s = 0; s < TOPK_; s++) {
            unsigned long long m = ka > kb ? ka : kb;
            #pragma unroll
            for (int o = 16; o; o >>= 1) {
                unsigned long long t = __shfl_xor_sync(0xFFFFFFFFu, m, o);
                if (t > m) m = t;
            }
            if (ka == m) {
                int idx = ci[lane]; float v = cv[lane];
                enc[(size_t)row * DICT_ + idx] = v;
                g_vals[row * TOPK_ + s] = v;
                g_idx [row * TOPK_ + s] = idx;
                ka = 0ull;
            } else if (kb == m) {
                int idx = ci[lane + 32]; float v = cv[lane + 32];
                enc[(size_t)row * DICT_ + idx] = v;
                g_vals[row * TOPK_ + s] = v;
                g_idx [row * TOPK_ + s] = idx;
                kb = 0ull;
            }
        }
    }
}

// ---------------------------------------------------------------------------
// W_dec [DIM, DICT] -> g_WdT [DICT, DIM]
// ---------------------------------------------------------------------------
__global__ void transpose_wdec(const float* __restrict__ Wd)
{
    __shared__ float tile[32][33];
    int bx = blockIdx.x * 32;
    int by = blockIdx.y * 32;
    int tx = threadIdx.x, ty = threadIdx.y;
    #pragma unroll
    for (int j = 0; j < 32; j += 8)
        tile[ty + j][tx] = Wd[(size_t)(by + ty + j) * DICT_ + bx + tx];
    __syncthreads();
    #pragma unroll
    for (int j = 0; j < 32; j += 8)
        g_WdT[(size_t)(bx + ty + j) * DIM_ + by + tx] = tile[tx][ty + j];
}

// ---------------------------------------------------------------------------
// Decode + loss
// ---------------------------------------------------------------------------
__global__ __launch_bounds__(256) void decode_kernel(
    const float* __restrict__ X, const float* __restrict__ b_dec,
    float* __restrict__ rec, float* __restrict__ loss)
{
    const int row = blockIdx.x;
    const int tid = threadIdx.x;
    __shared__ float sv[TOPK_];
    __shared__ int   si[TOPK_];
    if (tid < TOPK_) { sv[tid] = g_vals[row * TOPK_ + tid];
                       si[tid] = g_idx [row * TOPK_ + tid]; }
    __syncthreads();

    float acc[3];
    #pragma unroll
    for (int j = 0; j < 3; j++) acc[j] = b_dec[tid + j * 256];

    for (int kk = 0; kk < TOPK_; kk++) {
        const float* w = g_WdT + (size_t)si[kk] * DIM_;
        float v = sv[kk];
        #pragma unroll
        for (int j = 0; j < 3; j++)
            acc[j] = fmaf(v, w[tid + j * 256], acc[j]);
    }

    float err = 0.f;
    #pragma unroll
    for (int j = 0; j < 3; j++) {
        int d = tid + j * 256;
        float r = acc[j];
        rec[(size_t)row * DIM_ + d] = r;
        float diff = r - X[(size_t)row * DIM_ + d];
        err = fmaf(diff, diff, err);
    }
    #pragma unroll
    for (int o = 16; o; o >>= 1) err += __shfl_xor_sync(0xFFFFFFFFu, err, o);
    __shared__ float ws[8];
    if ((tid & 31) == 0) ws[tid >> 5] = err;
    __syncthreads();
    if (tid < 8) {
        float e = ws[tid];
        #pragma unroll
        for (int o = 4; o; o >>= 1) e += __shfl_xor_sync(0xFFu, e, o);
        if (tid == 0) atomicAdd(loss, e * (1.0f / BATCH_));
    }
}

__global__ void zero_loss(float* loss) { if (threadIdx.x == 0) *loss = 0.f; }

// ---------------------------------------------------------------------------
// kernel_launch
// ---------------------------------------------------------------------------
extern "C" void kernel_launch(void* const* d_in, const int* in_sizes, int n_in,
                              void* d_out, int out_size)
{
    const float* X     = (const float*)d_in[0];
    const float* W_enc = (const float*)d_in[1];
    const float* b_enc = (const float*)d_in[2];
    const float* W_dec = (const float*)d_in[3];
    const float* b_dec = (const float*)d_in[4];

    float* out  = (float*)d_out;
    float* rec  = out;
    float* enc  = out + (size_t)BATCH_ * DIM_;
    float* loss = enc + (size_t)BATCH_ * DICT_;

    cudaFuncSetAttribute(topk_cand,
                         cudaFuncAttributeMaxDynamicSharedMemorySize,
                         DICT_ * 2);
    cudaFuncSetAttribute(encode_gemm_mma,
                         cudaFuncAttributeMaxDynamicSharedMemorySize,
                         SMEM_GEMM);

    zero_enc<<<(int)((size_t)BATCH_ * DICT_ / 4 / 256), 256>>>(enc);
    cvt_x<<<(BATCH_ * DIM_ / 4 + 255) / 256, 256>>>(X);
    cvt_w<<<(DICT_ * DIM_ / 4 + 255) / 256, 256>>>(W_enc);

    dim3 gg(BATCH_ / TM, DICT_ / TN);
    encode_gemm_mma<<<gg, 256, SMEM_GEMM>>>(b_enc);

    topk_cand<<<BATCH_, 256, DICT_ * 2>>>();
    refine_kernel<<<BATCH_, 256>>>(X, W_enc, b_enc, enc);
    transpose_wdec<<<dim3(DICT_ / 32, DIM_ / 32), dim3(32, 8)>>>(W_dec);
    zero_loss<<<1, 32>>>(loss);
    decode_kernel<<<BATCH_, 256>>>(X, b_dec, rec, loss);
}